// round 10
// baseline (speedup 1.0000x reference)
#include <cuda_runtime.h>
#include <cstdint>

#define NCOLS 8192
#define NROWS 8192
#define SEQ 8                 // rows processed per CTA (pipelined)
#define THREADS 512
#define NWARP (THREADS / 32)

__global__ __launch_bounds__(THREADS) void a4_quant_kernel(
    const float* __restrict__ x, const int* __restrict__ perm,
    float* __restrict__ out)
{
    // Two 32 KB row buffers (dynamic smem, 64 KB total => 3 CTAs/SM).
    extern __shared__ float sbuf[];   // [2][NCOLS]
    const size_t rowbase = (size_t)blockIdx.x * SEQ;

    const int lane = threadIdx.x & 31;
    const int warp = threadIdx.x >> 5;

    // ---- Permutation dtype sniff (warp-uniform, L1/L2-hot) ----
    // As int32 words: an int64 perm (values < 8192) has all-zero odd words;
    // an int32 perm has at most one zero among any 64 odd words.
    const int hiw = perm[2 * lane + 1] | perm[2 * lane + 65];
    const bool is64 = (__ballot_sync(0xffffffffu, hiw != 0) == 0u);

    const unsigned sb = (unsigned)__cvta_generic_to_shared(sbuf);

    // Stage one full row into buffer b via cp.async (4 x 16B per thread).
    auto stage = [&](int b, int r) {
        const char* src = (const char*)(x + (rowbase + r) * NCOLS);
        const unsigned dst = sb + (unsigned)b * (NCOLS * 4);
        #pragma unroll
        for (int it = 0; it < NCOLS / 4 / THREADS; ++it) {
            const int i = it * THREADS + threadIdx.x;
            asm volatile("cp.async.cg.shared.global [%0], [%1], 16;\n"
                         :: "r"(dst + i * 16), "l"(src + (size_t)i * 16));
        }
        asm volatile("cp.async.commit_group;\n" ::: "memory");
    };

    // Prologue: stage row 0 into buffer 0.
    stage(0, 0);

    const int kblk = lane >> 3;   // which of the warp's 4 blocks this lane serves
    const int g    = lane & 7;    // lane within the 8-lane block group

    #pragma unroll 1
    for (int r = 0; r < SEQ; ++r) {
        // Stage next row into the other buffer, then wait for current row.
        if (r + 1 < SEQ) {
            stage((r + 1) & 1, r + 1);
            asm volatile("cp.async.wait_group 1;\n" ::: "memory");
        } else {
            asm volatile("cp.async.wait_group 0;\n" ::: "memory");
        }
        __syncthreads();

        const float* rowp = sbuf + (r & 1) * NCOLS;
        float* orow = out + (rowbase + r) * NCOLS;

        // Warp iteration covers a 128-column span = 4 quant blocks of 32.
        // Lanes 8k..8k+7 own block k; lane handles 4 consecutive columns.
        for (int s = warp; s < NCOLS / 128; s += NWARP) {
            const int col0 = (s * 4 + kblk) * 32 + g * 4;

            // Index load straight from the input buffer (L1/L2-hot)
            int4 c4;
            if (is64) {
                const int4 a = *(const int4*)(perm + 2 * col0);
                const int4 b = *(const int4*)(perm + 2 * col0 + 4);
                c4 = make_int4(a.x, a.z, b.x, b.z);   // low words of 4 int64s
            } else {
                c4 = *(const int4*)(perm + col0);
            }

            // Random-bank LDS.32 gather, 4-way ILP
            const unsigned b0 = __float_as_uint(rowp[c4.x]);
            const unsigned b1 = __float_as_uint(rowp[c4.y]);
            const unsigned b2 = __float_as_uint(rowp[c4.z]);
            const unsigned b3 = __float_as_uint(rowp[c4.w]);

            const unsigned u0 = b0 & 0x7fffffffu;
            const unsigned u1 = b1 & 0x7fffffffu;
            const unsigned u2 = b2 & 0x7fffffffu;
            const unsigned u3 = b3 & 0x7fffffffu;

            // Block amax (uint max == float max for abs bits): local then
            // 8-lane butterfly reduce.
            unsigned um = max(max(u0, u1), max(u2, u3));
            um = max(um, __shfl_xor_sync(0xffffffffu, um, 1));
            um = max(um, __shfl_xor_sync(0xffffffffu, um, 2));
            um = max(um, __shfl_xor_sync(0xffffffffu, um, 4));

            // Clamp amax exponent so threshold arithmetic never underflows
            // (only reachable for amax < 2^-122; abs err < 2^-122).
            const unsigned m2   = max(um, 0x02800000u);
            const unsigned mexp = m2 & 0x7f800000u;      // 2^E bits
            const unsigned six  = mexp | 0x00400000u;    // 6   * 2^(E-2)
            const unsigned one  = mexp - 0x01000000u;    // 1   * 2^(E-2)
            const unsigned half = mexp - 0x01800000u;    // 0.5 * 2^(E-2)
            const unsigned t075 = half | 0x00400000u;    // 0.75* 2^(E-2)
            const unsigned t025 = mexp - 0x02000000u;    // 0.25* 2^(E-2)

            // FP4 E2M1 quantization in output scale, ties round UP
            // (matches searchsorted(FP4_MID, mag, side="right")).
            uint4 qv;
            {
                const unsigned c = min(u0, six);
                const unsigned rb = (c + 0x00200000u) & 0xffc00000u;
                const unsigned q = (u0 >= one) ? rb
                                 : (u0 >= t075) ? one
                                 : (u0 >= t025) ? half : 0u;
                qv.x = q | (b0 & 0x80000000u);
            }
            {
                const unsigned c = min(u1, six);
                const unsigned rb = (c + 0x00200000u) & 0xffc00000u;
                const unsigned q = (u1 >= one) ? rb
                                 : (u1 >= t075) ? one
                                 : (u1 >= t025) ? half : 0u;
                qv.y = q | (b1 & 0x80000000u);
            }
            {
                const unsigned c = min(u2, six);
                const unsigned rb = (c + 0x00200000u) & 0xffc00000u;
                const unsigned q = (u2 >= one) ? rb
                                 : (u2 >= t075) ? one
                                 : (u2 >= t025) ? half : 0u;
                qv.z = q | (b2 & 0x80000000u);
            }
            {
                const unsigned c = min(u3, six);
                const unsigned rb = (c + 0x00200000u) & 0xffc00000u;
                const unsigned q = (u3 >= one) ? rb
                                 : (u3 >= t075) ? one
                                 : (u3 >= t025) ? half : 0u;
                qv.w = q | (b3 & 0x80000000u);
            }

            // STG.128 of 4 consecutive output columns
            *(uint4*)(orow + col0) = qv;
        }
        __syncthreads();   // buffer (r&1) free for reuse at iteration r+2
    }
}

extern "C" void kernel_launch(void* const* d_in, const int* in_sizes, int n_in,
                              void* d_out, int out_size)
{
    // Identify inputs by element count (x: 8192*8192, permutation: 8192)
    const float* x     = nullptr;
    const void*  permb = nullptr;
    if (n_in >= 2 && in_sizes[0] == NCOLS) {
        permb = d_in[0];
        x     = (const float*)d_in[1];
    } else {
        x     = (const float*)d_in[0];
        permb = d_in[1];
    }
    float* out = (float*)d_out;

    const int smem_bytes = 2 * NCOLS * (int)sizeof(float);  // 64 KB
    cudaFuncSetAttribute(a4_quant_kernel,
                         cudaFuncAttributeMaxDynamicSharedMemorySize, smem_bytes);
    a4_quant_kernel<<<NROWS / SEQ, THREADS, smem_bytes>>>(
        x, (const int*)permb, out);
}

// round 11
// speedup vs baseline: 1.1842x; 1.1842x over previous
#include <cuda_runtime.h>
#include <cstdint>

#define NCOLS 8192
#define NROWS 8192
#define ROWS_PER_CTA 2
#define THREADS 512
#define NWARP (THREADS / 32)

__global__ __launch_bounds__(THREADS) void a4_quant_kernel(
    const float* __restrict__ x, const int* __restrict__ perm,
    float* __restrict__ out)
{
    extern __shared__ float srow[];  // ROWS_PER_CTA * NCOLS floats = 64 KB
    const size_t row0 = (size_t)blockIdx.x * ROWS_PER_CTA;

    // ---- Permutation dtype sniff (warp-uniform, L1/L2-hot) ----
    // As int32 words: an int64 perm (values < 8192) has all-zero odd words;
    // an int32 perm has at most one zero among any 64 odd words.
    const int lane = threadIdx.x & 31;
    const int hiw = perm[2 * lane + 1] | perm[2 * lane + 65];
    const bool is64 = (__ballot_sync(0xffffffffu, hiw != 0) == 0u);

    // ---- Stage ROWS_PER_CTA rows into SMEM via cp.async ----
    {
        const char* src = (const char*)(x + row0 * NCOLS);
        unsigned s = (unsigned)__cvta_generic_to_shared(srow);
        #pragma unroll
        for (int i = threadIdx.x; i < ROWS_PER_CTA * NCOLS / 4; i += THREADS) {
            asm volatile("cp.async.cg.shared.global [%0], [%1], 16;\n"
                         :: "r"(s + i * 16), "l"(src + (size_t)i * 16));
        }
        asm volatile("cp.async.commit_group;\n"
                     "cp.async.wait_group 0;\n" ::: "memory");
    }
    __syncthreads();

    const int warp = threadIdx.x >> 5;
    const int kblk = lane >> 3;   // which of the warp's 4 blocks this lane serves
    const int g    = lane & 7;    // lane within the 8-lane block group

    // Warp iteration covers a 128-column span = 4 quant blocks of 32.
    // Lanes 8k..8k+7 own block k; lane handles 4 consecutive columns.
    for (int s = warp; s < NCOLS / 128; s += NWARP) {
        const int col0 = (s * 4 + kblk) * 32 + g * 4;

        // Index load straight from the input buffer (L1/L2-hot)
        int4 c4;
        if (is64) {
            const int4 a = *(const int4*)(perm + 2 * col0);
            const int4 b = *(const int4*)(perm + 2 * col0 + 4);
            c4 = make_int4(a.x, a.z, b.x, b.z);   // low words of 4 int64s
        } else {
            c4 = *(const int4*)(perm + col0);
        }

        #pragma unroll
        for (int rr = 0; rr < ROWS_PER_CTA; ++rr) {
            const float* rowp = srow + rr * NCOLS;

            // Random-bank LDS.32 gather, 4-way ILP
            const unsigned b0 = __float_as_uint(rowp[c4.x]);
            const unsigned b1 = __float_as_uint(rowp[c4.y]);
            const unsigned b2 = __float_as_uint(rowp[c4.z]);
            const unsigned b3 = __float_as_uint(rowp[c4.w]);

            const unsigned u0 = b0 & 0x7fffffffu;
            const unsigned u1 = b1 & 0x7fffffffu;
            const unsigned u2 = b2 & 0x7fffffffu;
            const unsigned u3 = b3 & 0x7fffffffu;

            // Block amax (uint max == float max for abs bits): local then
            // 8-lane butterfly reduce.
            unsigned um = max(max(u0, u1), max(u2, u3));
            um = max(um, __shfl_xor_sync(0xffffffffu, um, 1));
            um = max(um, __shfl_xor_sync(0xffffffffu, um, 2));
            um = max(um, __shfl_xor_sync(0xffffffffu, um, 4));

            // Clamp amax exponent so threshold arithmetic never underflows
            // (only reachable for amax < 2^-122; abs err < 2^-122).
            const unsigned m2   = max(um, 0x02800000u);
            const unsigned mexp = m2 & 0x7f800000u;      // 2^E bits
            const unsigned six  = mexp | 0x00400000u;    // 6   * 2^(E-2)
            const unsigned one  = mexp - 0x01000000u;    // 1   * 2^(E-2)
            const unsigned half = mexp - 0x01800000u;    // 0.5 * 2^(E-2)
            const unsigned t075 = half | 0x00400000u;    // 0.75* 2^(E-2)
            const unsigned t025 = mexp - 0x02000000u;    // 0.25* 2^(E-2)

            // FP4 E2M1 quantization in output scale, ties round UP
            // (matches searchsorted(FP4_MID, mag, side="right")).
            uint4 qv;
            {
                const unsigned c = min(u0, six);
                const unsigned r = (c + 0x00200000u) & 0xffc00000u;
                const unsigned q = (u0 >= one) ? r
                                 : (u0 >= t075) ? one
                                 : (u0 >= t025) ? half : 0u;
                qv.x = q | (b0 & 0x80000000u);
            }
            {
                const unsigned c = min(u1, six);
                const unsigned r = (c + 0x00200000u) & 0xffc00000u;
                const unsigned q = (u1 >= one) ? r
                                 : (u1 >= t075) ? one
                                 : (u1 >= t025) ? half : 0u;
                qv.y = q | (b1 & 0x80000000u);
            }
            {
                const unsigned c = min(u2, six);
                const unsigned r = (c + 0x00200000u) & 0xffc00000u;
                const unsigned q = (u2 >= one) ? r
                                 : (u2 >= t075) ? one
                                 : (u2 >= t025) ? half : 0u;
                qv.z = q | (b2 & 0x80000000u);
            }
            {
                const unsigned c = min(u3, six);
                const unsigned r = (c + 0x00200000u) & 0xffc00000u;
                const unsigned q = (u3 >= one) ? r
                                 : (u3 >= t075) ? one
                                 : (u3 >= t025) ? half : 0u;
                qv.w = q | (b3 & 0x80000000u);
            }

            // STG.128 of 4 consecutive output columns
            *(uint4*)(out + (row0 + rr) * NCOLS + col0) = qv;
        }
    }
}

extern "C" void kernel_launch(void* const* d_in, const int* in_sizes, int n_in,
                              void* d_out, int out_size)
{
    // Identify inputs by element count (x: 8192*8192, permutation: 8192)
    const float* x     = nullptr;
    const void*  permb = nullptr;
    if (n_in >= 2 && in_sizes[0] == NCOLS) {
        permb = d_in[0];
        x     = (const float*)d_in[1];
    } else {
        x     = (const float*)d_in[0];
        permb = d_in[1];
    }
    float* out = (float*)d_out;

    const int smem_bytes = ROWS_PER_CTA * NCOLS * (int)sizeof(float);  // 64 KB
    cudaFuncSetAttribute(a4_quant_kernel,
                         cudaFuncAttributeMaxDynamicSharedMemorySize, smem_bytes);
    a4_quant_kernel<<<NROWS / ROWS_PER_CTA, THREADS, smem_bytes>>>(
        x, (const int*)permb, out);
}